// round 5
// baseline (speedup 1.0000x reference)
#include <cuda_runtime.h>

// Shapes (this instance): B=2048, L=196, M=16, NBL=10. Derived from in_sizes.
#define MAXSITES 256          // >= L-2 (=194)
#define MAXB     4096         // >= B   (=2048)

// Single packed site tensor (shared by both sweep directions):
//   PACK[s][r*8+c] = {A0[r][c], A0[r][c+8], A1[r][c], A1[r][c+8]}
__device__ float4 g_PACK[MAXSITES * 128];
__device__ float  g_left [MAXB * 16];
__device__ float  g_right[MAXB * 16];

// ---------------------------------------------------------------------------
// f32x2 helpers
// ---------------------------------------------------------------------------
typedef unsigned long long ull;
__device__ __forceinline__ ull pack2(float x, float y) {
    ull r; asm("mov.b64 %0, {%1,%2};" : "=l"(r) : "f"(x), "f"(y)); return r;
}
__device__ __forceinline__ void unpack2(ull v, float& x, float& y) {
    asm("mov.b64 {%0,%1}, %2;" : "=f"(x), "=f"(y) : "l"(v));
}
__device__ __forceinline__ void fma2(ull& d, ull a, ull b) {
    asm("fma.rn.f32x2 %0, %1, %2, %0;" : "+l"(d) : "l"(a), "l"(b));
}
__device__ __forceinline__ ull mul2(ull a, ull b) {
    ull d; asm("mul.rn.f32x2 %0, %1, %2;" : "=l"(d) : "l"(a), "l"(b)); return d;
}
__device__ __forceinline__ ull add2(ull a, ull b) {
    ull d; asm("add.rn.f32x2 %0, %1, %2;" : "=l"(d) : "l"(a), "l"(b)); return d;
}
__device__ __forceinline__ float hsum2(ull a) {
    float x, y; unpack2(a, x, y); return x + y;
}

// ---------------------------------------------------------------------------
// Kernel 1: repack A_mid (Lm2,2,16,16) -> PACK. One 128-thr block per site.
// ---------------------------------------------------------------------------
__global__ void __launch_bounds__(128)
prep_kernel(const float* __restrict__ A_mid, int Lm2) {
    __shared__ __align__(16) float sA[512];
    int s = blockIdx.x;
    int t = threadIdx.x;
    ((float4*)sA)[t] = __ldg((const float4*)(A_mid + s * 512) + t);
    __syncthreads();
    int r = t >> 3, c = t & 7;
    float4 o;
    o.x = sA[r * 16 + c];
    o.y = sA[r * 16 + c + 8];
    o.z = sA[256 + r * 16 + c];
    o.w = sA[256 + r * 16 + c + 8];
    g_PACK[s * 128 + t] = o;
}

// ---------------------------------------------------------------------------
// Kernel 2: chain contraction. Warps fully independent (no block barriers).
// Warp = 4 chains; lane: q = lane&7 (component pair {q, q+8}), lc = lane>>3.
// Per-warp smem: double-buffered matrix tile (bank-padded) + double-buffered v.
// One __syncwarp per site. All smem rows are 16B-aligned (strides: MROW float4,
// 18 float2 = 144B, 10 ull = 80B).
// ---------------------------------------------------------------------------
#define MROW 9   // 8 float4 per row + 1 pad (16B) -> 144B row stride

__global__ void __launch_bounds__(128)
chain_kernel(const float* __restrict__ inputs,
             const float* __restrict__ A_left,
             const float* __restrict__ A_right,
             const int*   __restrict__ pos_ptr,
             int B, int L) {
    __shared__ __align__(16) float4 sMat[4][2][16 * MROW];  // [warp][buf]
    __shared__ __align__(16) float2 sVs [4][2][4][18];      // left: splatted v
    __shared__ __align__(16) ull    sVn [4][2][4][10];      // right: natural v

    int tid  = threadIdx.x;
    int w    = tid >> 5;
    int lane = tid & 31;
    int q    = lane & 7;
    int lc   = lane >> 3;

    int pos = __ldg(pos_ptr);
    int Lm2 = L - 2;
    int nLeftBlocks = B >> 4;
    bool isLeft = (blockIdx.x < (unsigned)nLeftBlocks);
    int blk = isLeft ? blockIdx.x : blockIdx.x - nLeftBlocks;
    int c   = blk * 16 + w * 4 + lc;           // global sample
    int nsites = isLeft ? pos : (Lm2 - pos);

    const float*  seedA = isLeft ? A_left : A_right;
    const float2* in2   = (const float2*)inputs;   // (B,L) float2
    int seedSite = isLeft ? 0 : (L - 1);

    // seed: v[n] = x0*Aseed[0][n] + x1*Aseed[1][n]
    float2 xs = __ldg(in2 + c * L + seedSite);
    float v0 = fmaf(xs.y, __ldg(seedA + 16 + q),     xs.x * __ldg(seedA + q));
    float v1 = fmaf(xs.y, __ldg(seedA + 16 + q + 8), xs.x * __ldg(seedA + q + 8));

    if (nsites > 0) {
        // ---- prologue: stage first site -> buf 0; seed v -> vbuf 0 ----
        {
            int a0 = isLeft ? 0 : (Lm2 - 1);
            const float4* src = g_PACK + a0 * 128;
#pragma unroll
            for (int k = 0; k < 4; ++k) {
                int idx = lane + k * 32;
                float4 m = __ldg(src + idx);
                sMat[w][0][(idx >> 3) * MROW + (idx & 7)] = m;
            }
        }
        if (isLeft) {
            sVs[w][0][lc][q]     = make_float2(v0, v0);
            sVs[w][0][lc][q + 8] = make_float2(v1, v1);
        } else {
            sVn[w][0][lc][q] = pack2(v0, v1);
        }

        if (isLeft) {
            // ============ LEFT sweep: v_new[n] = sum_m v[m]*M[m][n] ==========
            for (int s = 0; s < nsites; ++s) {
                int p = s & 1;
                __syncwarp();

                // prefetch next site's matrix (LDG now, STS after compute)
                float4 pre[4];
                bool more = (s + 1 < nsites);
                if (more) {
                    const float4* src = g_PACK + (s + 1) * 128;
#pragma unroll
                    for (int k = 0; k < 4; ++k)
                        pre[k] = __ldg(src + lane + k * 32);
                }

                // v splats (8 x LDS.128, 16B-aligned, conflict-free)
                ull vs[16];
                {
                    const ulonglong2* vp = (const ulonglong2*)&sVs[w][p][lc][0];
#pragma unroll
                    for (int j = 0; j < 8; ++j) {
                        ulonglong2 t = vp[j];
                        vs[2 * j]     = t.x;
                        vs[2 * j + 1] = t.y;
                    }
                }
                float2 x = __ldg(in2 + c * L + (1 + s));
                ull xx0 = pack2(x.x, x.x);
                ull xx1 = pack2(x.y, x.y);

                const float4* mrow = &sMat[w][p][0];
                ull aA0 = 0ull, aA1 = 0ull, aB0 = 0ull, aB1 = 0ull;
#pragma unroll
                for (int r = 0; r < 16; r += 2) {
                    ulonglong2 m0 = *(const ulonglong2*)&mrow[r * MROW + q];
                    ulonglong2 m1 = *(const ulonglong2*)&mrow[(r + 1) * MROW + q];
                    fma2(aA0, vs[r],     m0.x);
                    fma2(aB0, vs[r],     m0.y);
                    fma2(aA1, vs[r + 1], m1.x);
                    fma2(aB1, vs[r + 1], m1.y);
                }
                ull tt = mul2(xx0, add2(aA0, aA1));
                fma2(tt, xx1, add2(aB0, aB1));
                unpack2(tt, v0, v1);

                if (more) {
#pragma unroll
                    for (int k = 0; k < 4; ++k) {
                        int idx = lane + k * 32;
                        sMat[w][1 - p][(idx >> 3) * MROW + (idx & 7)] = pre[k];
                    }
                }
                sVs[w][1 - p][lc][q]     = make_float2(v0, v0);
                sVs[w][1 - p][lc][q + 8] = make_float2(v1, v1);
            }
        } else {
            // ============ RIGHT sweep: v_new[m] = sum_n M[m][n]*v[n] =========
            for (int s = 0; s < nsites; ++s) {
                int p = s & 1;
                __syncwarp();

                float4 pre[4];
                bool more = (s + 1 < nsites);
                if (more) {
                    const float4* src = g_PACK + (Lm2 - 2 - s) * 128;
#pragma unroll
                    for (int k = 0; k < 4; ++k)
                        pre[k] = __ldg(src + lane + k * 32);
                }

                // natural v pairs (4 x LDS.128, 16B-aligned)
                ull vpair[8];
                {
                    const ulonglong2* vp = (const ulonglong2*)&sVn[w][p][lc][0];
#pragma unroll
                    for (int j = 0; j < 4; ++j) {
                        ulonglong2 t = vp[j];
                        vpair[2 * j]     = t.x;
                        vpair[2 * j + 1] = t.y;
                    }
                }
                float2 x = __ldg(in2 + c * L + (L - 2 - s));

                const float4* rowq  = &sMat[w][p][q * MROW];
                const float4* rowq8 = &sMat[w][p][(q + 8) * MROW];
                ull a0 = 0ull, a1 = 0ull, b0 = 0ull, b1 = 0ull;
#pragma unroll
                for (int cc = 0; cc < 8; ++cc) {
                    ulonglong2 mq  = *(const ulonglong2*)&rowq[cc];
                    ulonglong2 mq8 = *(const ulonglong2*)&rowq8[cc];
                    fma2(a0, vpair[cc], mq.x);
                    fma2(a1, vpair[cc], mq.y);
                    fma2(b0, vpair[cc], mq8.x);
                    fma2(b1, vpair[cc], mq8.y);
                }
                v0 = fmaf(x.y, hsum2(a1), x.x * hsum2(a0));
                v1 = fmaf(x.y, hsum2(b1), x.x * hsum2(b0));

                if (more) {
#pragma unroll
                    for (int k = 0; k < 4; ++k) {
                        int idx = lane + k * 32;
                        sMat[w][1 - p][(idx >> 3) * MROW + (idx & 7)] = pre[k];
                    }
                }
                sVn[w][1 - p][lc][q] = pack2(v0, v1);
            }
        }
    }

    float* out = isLeft ? g_left : g_right;
    out[c * 16 + q]     = v0;
    out[c * 16 + q + 8] = v1;
}

// ---------------------------------------------------------------------------
// Kernel 3: out[b][l] = sum_{m,k} left[b][m] * T[m][k][l] * right[b][k]
// ---------------------------------------------------------------------------
__global__ void __launch_bounds__(256)
combine_kernel(const float* __restrict__ T,
               float* __restrict__ out,
               int B, int NBL) {
    __shared__ float sT[4096];            // >= 16*16*NBL (NBL<=16)
    int tid = threadIdx.x;
    int tElems = 256 * NBL;
    for (int i = tid; i < tElems; i += blockDim.x) sT[i] = T[i];
    __syncthreads();

    int idx = blockIdx.x * blockDim.x + tid;
    if (idx >= B * NBL) return;
    int b = idx / NBL;
    int l = idx - b * NBL;

    float lv[16], rv[16];
#pragma unroll
    for (int k = 0; k < 16; ++k) {
        lv[k] = g_left [b * 16 + k];
        rv[k] = g_right[b * 16 + k];
    }
    float s = 0.f;
#pragma unroll
    for (int m = 0; m < 16; ++m) {
        float t = 0.f;
#pragma unroll
        for (int k = 0; k < 16; ++k)
            t = fmaf(sT[(m * 16 + k) * NBL + l], rv[k], t);
        s = fmaf(lv[m], t, s);
    }
    out[idx] = s;
}

// ---------------------------------------------------------------------------
extern "C" void kernel_launch(void* const* d_in, const int* in_sizes, int n_in,
                              void* d_out, int out_size) {
    const float* inputs  = (const float*)d_in[0];
    const float* A_left  = (const float*)d_in[1];
    const float* A_mid   = (const float*)d_in[2];
    const float* A_right = (const float*)d_in[3];
    const float* T_out   = (const float*)d_in[4];
    const int*   pos     = (const int*)d_in[5];

    int Lm2 = in_sizes[2] / 512;          // L-2 = 194
    int L   = Lm2 + 2;                    // 196
    int B   = in_sizes[0] / (2 * L);      // 2048
    int NBL = in_sizes[4] / 256;          // 10

    prep_kernel<<<Lm2, 128>>>(A_mid, Lm2);

    // 16 chains/block per side -> 2*(B/16) blocks of 128 threads
    chain_kernel<<<B / 8, 128>>>(inputs, A_left, A_right, pos, B, L);

    int total = B * NBL;
    combine_kernel<<<(total + 255) / 256, 256>>>(T_out, (float*)d_out, B, NBL);
}

// round 6
// speedup vs baseline: 1.2144x; 1.2144x over previous
#include <cuda_runtime.h>

// Shapes (this instance): B=2048, L=196, M=16, NBL=10. Derived from in_sizes.
#define MAXSITES 256          // >= L-2 (=194)
#define MAXB     4096         // >= B   (=2048)

// Pre-paired site tensors for f32x2 math (validated in R3):
//   mat4[s][m*8+q] = {A0[m][q], A0[m][q+8], A1[m][q], A1[m][q+8]}
// L: forward order; R: reversed + transposed (right sweep runs forward form).
__device__ float4 g_mat4L[MAXSITES * 128];
__device__ float4 g_mat4R[MAXSITES * 128];
__device__ float  g_left [MAXB * 16];
__device__ float  g_right[MAXB * 16];

// ---------------------------------------------------------------------------
// f32x2 helpers
// ---------------------------------------------------------------------------
typedef unsigned long long ull;
__device__ __forceinline__ ull pack2(float x, float y) {
    ull r; asm("mov.b64 %0, {%1,%2};" : "=l"(r) : "f"(x), "f"(y)); return r;
}
__device__ __forceinline__ void unpack2(ull v, float& x, float& y) {
    asm("mov.b64 {%0,%1}, %2;" : "=f"(x), "=f"(y) : "l"(v));
}
__device__ __forceinline__ void fma2(ull& d, ull a, ull b) {
    asm("fma.rn.f32x2 %0, %1, %2, %0;" : "+l"(d) : "l"(a), "l"(b));
}
__device__ __forceinline__ ull mul2(ull a, ull b) {
    ull d; asm("mul.rn.f32x2 %0, %1, %2;" : "=l"(d) : "l"(a), "l"(b)); return d;
}
__device__ __forceinline__ ull add2(ull a, ull b) {
    ull d; asm("add.rn.f32x2 %0, %1, %2;" : "=l"(d) : "l"(a), "l"(b)); return d;
}

// ---------------------------------------------------------------------------
// cp.async helpers
// ---------------------------------------------------------------------------
__device__ __forceinline__ void cpasync16(unsigned dst, const void* src) {
    asm volatile("cp.async.cg.shared.global [%0], [%1], 16;\n"
                 :: "r"(dst), "l"(src) : "memory");
}
__device__ __forceinline__ void cpcommit() {
    asm volatile("cp.async.commit_group;\n" ::: "memory");
}
template<int N> __device__ __forceinline__ void cpwait() {
    asm volatile("cp.async.wait_group %0;\n" :: "n"(N) : "memory");
}

// ---------------------------------------------------------------------------
// Kernel 1: repack A_mid (Lm2,2,16,16) into paired float4 layout (R3-validated).
// ---------------------------------------------------------------------------
__global__ void __launch_bounds__(256)
prep_kernel(const float* __restrict__ A_mid, int Lm2) {
    int t = threadIdx.x;
    int s = blockIdx.x * 2 + (t >> 7);
    if (s >= Lm2) return;
    int e = t & 127;            // m*8+q
    int m = e >> 3, q = e & 7;
    const float* A0 = A_mid + s * 512;
    const float* A1 = A0 + 256;
    float4 L4 = make_float4(A0[m * 16 + q], A0[m * 16 + q + 8],
                            A1[m * 16 + q], A1[m * 16 + q + 8]);
    float4 R4 = make_float4(A0[q * 16 + m], A0[(q + 8) * 16 + m],
                            A1[q * 16 + m], A1[(q + 8) * 16 + m]);
    g_mat4L[s * 128 + e] = L4;
    g_mat4R[(Lm2 - 1 - s) * 128 + e] = R4;
}

// ---------------------------------------------------------------------------
// one site update: v(pair q,q+8 of chain ch) <- (x0*A0 + x1*A1)^T-contract
// mat: smem tile in paired float4 layout; in-warp v distribution via shfl.
// ---------------------------------------------------------------------------
__device__ __forceinline__ void site_step(const float4* __restrict__ mat,
                                          float2 x, int q, int ch,
                                          float& v0, float& v1) {
    ull a0e = 0ull, a0o = 0ull, a1e = 0ull, a1o = 0ull;
#pragma unroll
    for (int m = 0; m < 16; ++m) {
        float vm = (m < 8) ? __shfl_sync(0xffffffffu, v0, ch * 8 + m, 32)
                           : __shfl_sync(0xffffffffu, v1, ch * 8 + m - 8, 32);
        ull vmm = pack2(vm, vm);
        ulonglong2 M = *(const ulonglong2*)(mat + m * 8 + q);
        if (m & 1) { fma2(a0o, vmm, M.x); fma2(a1o, vmm, M.y); }
        else       { fma2(a0e, vmm, M.x); fma2(a1e, vmm, M.y); }
    }
    ull xx0 = pack2(x.x, x.x);
    ull xx1 = pack2(x.y, x.y);
    ull tt = mul2(xx0, add2(a0e, a0o));
    fma2(tt, xx1, add2(a1e, a1o));
    unpack2(tt, v0, v1);
}

// ---------------------------------------------------------------------------
// Kernel 2: chain contraction.
// Block = 256 thr (8 warps) = 32 chains, all same direction.
// Matrices staged block-wide via cp.async ring (3 pairs = 6 sites = 12KB);
// one __syncthreads per 2 sites. v lives in registers, distributed by shfl.
// ---------------------------------------------------------------------------
__global__ void __launch_bounds__(256)
chain_kernel(const float* __restrict__ inputs,
             const float* __restrict__ A_left,
             const float* __restrict__ A_right,
             const int*   __restrict__ pos_ptr,
             int B, int L) {
    __shared__ __align__(16) float4 ring[6 * 128];   // 3 pairs x 2 sites x 2KB

    int tid  = threadIdx.x;
    int w    = tid >> 5;
    int lane = tid & 31;
    int q    = lane & 7;
    int ch   = lane >> 3;                 // chain-in-warp 0..3

    int pos = __ldg(pos_ptr);
    int Lm2 = L - 2;
    int nLeftBlocks = B / 32;
    bool isLeft = (blockIdx.x < (unsigned)nLeftBlocks);
    int blk = isLeft ? blockIdx.x : blockIdx.x - nLeftBlocks;
    int c   = blk * 32 + w * 4 + ch;      // global sample
    int nsites = isLeft ? pos : (Lm2 - pos);

    const float4* mats  = isLeft ? g_mat4L : g_mat4R;
    const float*  seedA = isLeft ? A_left  : A_right;
    const float2* in2   = (const float2*)inputs;    // (B,L) float2
    int seedSite = isLeft ? 0 : (L - 1);

    // seed: v[n] = x0*Aseed[0][n] + x1*Aseed[1][n]
    float2 xs = __ldg(in2 + c * L + seedSite);
    float v0 = fmaf(xs.y, __ldg(seedA + 16 + q),     xs.x * __ldg(seedA + q));
    float v1 = fmaf(xs.y, __ldg(seedA + 16 + q + 8), xs.x * __ldg(seedA + q + 8));

    unsigned rb = (unsigned)__cvta_generic_to_shared(&ring[0]);

    // prologue: stage pairs 0,1 (sites 0..3), one commit group per pair
#pragma unroll
    for (int g = 0; g < 2; ++g) {
        int s0 = 2 * g;
        if (tid < 128) {
            if (s0 < nsites)
                cpasync16(rb + (2 * g) * 2048 + tid * 16,
                          (const char*)(mats + s0 * 128) + tid * 16);
            if (s0 + 1 < nsites)
                cpasync16(rb + (2 * g + 1) * 2048 + tid * 16,
                          (const char*)(mats + (s0 + 1) * 128) + tid * 16);
        }
        cpcommit();
    }

    int npairs = nsites >> 1;
    for (int t = 0; t < npairs; ++t) {
        cpwait<1>();            // pair t resident (pair t+1 may be in flight)
        __syncthreads();        // publish copies; pair t-1's slot now free

        int slot  = t % 3;
        int pslot = (t + 2) % 3;
        int sp = 2 * t + 4;     // first site of pair t+2
        if (tid < 128) {
            if (sp < nsites)
                cpasync16(rb + (2 * pslot) * 2048 + tid * 16,
                          (const char*)(mats + sp * 128) + tid * 16);
            if (sp + 1 < nsites)
                cpasync16(rb + (2 * pslot + 1) * 2048 + tid * 16,
                          (const char*)(mats + (sp + 1) * 128) + tid * 16);
        }
        cpcommit();

        int s0 = 2 * t;
        int xa = isLeft ? (1 + s0)     : (L - 2 - s0);
        int xb = isLeft ? (2 + s0)     : (L - 3 - s0);
        float2 x0 = __ldg(in2 + c * L + xa);
        float2 x1 = __ldg(in2 + c * L + xb);
        site_step(&ring[(2 * slot) * 128],     x0, q, ch, v0, v1);
        site_step(&ring[(2 * slot + 1) * 128], x1, q, ch, v0, v1);
    }

    if (nsites & 1) {           // tail site (even here, but stay generic)
        cpwait<1>();
        __syncthreads();
        int slot = npairs % 3;
        int s0 = nsites - 1;
        int xa = isLeft ? (1 + s0) : (L - 2 - s0);
        float2 x0 = __ldg(in2 + c * L + xa);
        site_step(&ring[(2 * slot) * 128], x0, q, ch, v0, v1);
    }
    cpwait<0>();                // drain before exit

    float* out = isLeft ? g_left : g_right;
    out[c * 16 + q]     = v0;
    out[c * 16 + q + 8] = v1;
}

// ---------------------------------------------------------------------------
// Kernel 3: out[b][l] = sum_{m,k} left[b][m] * T[m][k][l] * right[b][k]
// ---------------------------------------------------------------------------
__global__ void __launch_bounds__(256)
combine_kernel(const float* __restrict__ T,
               float* __restrict__ out,
               int B, int NBL) {
    __shared__ float sT[4096];            // >= 16*16*NBL (NBL<=16)
    int tid = threadIdx.x;
    int tElems = 256 * NBL;
    for (int i = tid; i < tElems; i += blockDim.x) sT[i] = T[i];
    __syncthreads();

    int idx = blockIdx.x * blockDim.x + tid;
    if (idx >= B * NBL) return;
    int b = idx / NBL;
    int l = idx - b * NBL;

    float lv[16], rv[16];
#pragma unroll
    for (int k = 0; k < 16; ++k) {
        lv[k] = g_left [b * 16 + k];
        rv[k] = g_right[b * 16 + k];
    }
    float s = 0.f;
#pragma unroll
    for (int m = 0; m < 16; ++m) {
        float t = 0.f;
#pragma unroll
        for (int k = 0; k < 16; ++k)
            t = fmaf(sT[(m * 16 + k) * NBL + l], rv[k], t);
        s = fmaf(lv[m], t, s);
    }
    out[idx] = s;
}

// ---------------------------------------------------------------------------
extern "C" void kernel_launch(void* const* d_in, const int* in_sizes, int n_in,
                              void* d_out, int out_size) {
    const float* inputs  = (const float*)d_in[0];
    const float* A_left  = (const float*)d_in[1];
    const float* A_mid   = (const float*)d_in[2];
    const float* A_right = (const float*)d_in[3];
    const float* T_out   = (const float*)d_in[4];
    const int*   pos     = (const int*)d_in[5];

    int Lm2 = in_sizes[2] / 512;          // L-2 = 194
    int L   = Lm2 + 2;                    // 196
    int B   = in_sizes[0] / (2 * L);      // 2048
    int NBL = in_sizes[4] / 256;          // 10

    prep_kernel<<<(Lm2 + 1) / 2, 256>>>(A_mid, Lm2);

    // 32 chains/block per side -> 2*(B/32) blocks of 256 threads
    chain_kernel<<<2 * (B / 32), 256>>>(inputs, A_left, A_right, pos, B, L);

    int total = B * NBL;
    combine_kernel<<<(total + 255) / 256, 256>>>(T_out, (float*)d_out, B, NBL);
}